// round 1
// baseline (speedup 1.0000x reference)
#include <cuda_runtime.h>
#include <cuda_bf16.h>
#include <math.h>

// Problem constants (fixed by setup_inputs)
#define Bsz 2
#define Hh  64
#define Ww  64
#define Ls  4096      // H*W
#define Cc  96
#define Kk  4
#define Nn  16
#define Rr  6
#define C38 38        // R + 2N
#define Sseg 32       // segments
#define Tseg 128      // steps per segment (S*T = L)
#define CH  16        // scan chunk staged through smem

// ---------------- scratch (static device globals; no allocation) -------------
__device__ float g_v[Bsz*Cc*Ls];          // v_img (b,c,l)
__device__ float g_delta[Bsz*Kk*Ls*Cc];   // (b,k,t,c)
__device__ float g_du[Bsz*Kk*Ls*Cc];      // delta*u
__device__ float g_Bv[Bsz*Kk*Ls*Nn];     // (b,k,t,n)
__device__ float g_Cv[Bsz*Kk*Ls*Nn];
__device__ float g_y[Bsz*Kk*Ls*Cc];       // scan output (b,k,t,c)
__device__ float g_hend[Bsz*Kk*Sseg*Cc*Nn];
__device__ float g_h0[Bsz*Kk*Sseg*Cc*Nn];
__device__ float g_sumd[Bsz*Kk*Sseg*Cc];
__device__ float g_att[Bsz*Ls*Cc];        // (b,l,c)
__device__ float g_convx[Bsz*Cc*Ls];      // (b,c,l)
__device__ float g_pool[Bsz*Cc];
__device__ float g_cmsig[Bsz*Cc];

__device__ __forceinline__ float sigmoidf_(float x){ return 1.0f/(1.0f+__expf(-x)); }

// ---------------- K1: v_img = (x @ qkv_w^T) transposed to (b,c,l) -----------
__global__ void k_qkv(const float* __restrict__ x, const float* __restrict__ qkv_w)
{
    __shared__ float sx[32][97];
    __shared__ float sw[96][97];
    int blk = blockIdx.x;
    int b   = blk / (Ls/32);
    int l0  = (blk % (Ls/32)) * 32;
    int c   = threadIdx.x;  // 96 threads

    for (int idx = c; idx < 96*96; idx += 96) {
        sw[idx/96][idx%96] = qkv_w[idx];
    }
    #pragma unroll
    for (int i = 0; i < 32; i++)
        sx[i][c] = x[(b*Ls + l0 + i)*Cc + c];
    __syncthreads();

    for (int l = 0; l < 32; l += 4) {
        float a0=0.f,a1=0.f,a2=0.f,a3=0.f;
        #pragma unroll
        for (int cp = 0; cp < 96; cp++) {
            float wv = sw[c][cp];
            a0 += sx[l+0][cp]*wv;
            a1 += sx[l+1][cp]*wv;
            a2 += sx[l+2][cp]*wv;
            a3 += sx[l+3][cp]*wv;
        }
        float* vp = &g_v[(b*Cc + c)*Ls + l0 + l];
        vp[0]=a0; vp[1]=a1; vp[2]=a2; vp[3]=a3;
    }
}

// ---------------- K2: projections (x_dbl -> delta, du, B, C) -----------------
__global__ void k_proj(const float* __restrict__ x_proj_w,
                       const float* __restrict__ dt_w,
                       const float* __restrict__ dt_b)
{
    __shared__ float sxs[32][97];
    __shared__ float swp[38][97];
    __shared__ float sxd[32][40];
    __shared__ float sdtw[96][8];
    __shared__ float sdtb[96];

    int tiles = Ls/32;
    int tile = blockIdx.x % tiles;
    int k    = (blockIdx.x / tiles) % Kk;
    int b    = blockIdx.x / (tiles*Kk);
    int c    = threadIdx.x;  // 96 threads
    int t0   = tile*32;

    for (int idx = c; idx < 38*96; idx += 96)
        swp[idx/96][idx%96] = x_proj_w[k*38*96 + idx];
    #pragma unroll
    for (int r = 0; r < 6; r++) sdtw[c][r] = dt_w[(k*Cc + c)*Rr + r];
    sdtb[c] = dt_b[k*Cc + c];

    #pragma unroll 4
    for (int i = 0; i < 32; i++) {
        int tg = t0 + i;
        int l;
        if      (k == 0) l = tg;
        else if (k == 1) { int hh = tg & 63, ww = tg >> 6; l = hh*64 + ww; }
        else if (k == 2) l = 4095 - tg;
        else             { int tt = 4095 - tg; int hh = tt & 63, ww = tt >> 6; l = hh*64 + ww; }
        sxs[i][c] = g_v[(b*Cc + c)*Ls + l];
    }
    __syncthreads();

    for (int p = c; p < 32*38; p += 96) {
        int i = p / 38, j = p % 38;
        float acc = 0.f;
        #pragma unroll
        for (int cp = 0; cp < 96; cp++) acc += sxs[i][cp]*swp[j][cp];
        sxd[i][j] = acc;
    }
    __syncthreads();

    int bk = b*Kk + k;
    for (int i = 0; i < 32; i++) {
        float acc = 0.f;
        #pragma unroll
        for (int r = 0; r < 6; r++) acc += sxd[i][r]*sdtw[c][r];
        float xv = acc + sdtb[c];
        float delta = (xv > 20.f) ? xv : log1pf(__expf(xv));
        int gi = (bk*Ls + t0 + i);
        g_delta[gi*Cc + c] = delta;
        g_du[gi*Cc + c]    = delta * sxs[i][c];
    }
    for (int p = c; p < 32*16; p += 96) {
        int i = p / 16, n = p % 16;
        int gi = (bk*Ls + t0 + i);
        g_Bv[gi*Nn + n] = sxd[i][6 + n];
        g_Cv[gi*Nn + n] = sxd[i][22 + n];
    }
}

// ---------------- K3: segmented selective scan -------------------------------
template<bool PASSB>
__global__ void k_scan(const float* __restrict__ A_logs)
{
    __shared__ float sD[CH][Cc];
    __shared__ float sU[CH][Cc];
    __shared__ float4 sB[CH][4];
    __shared__ float4 sCs[CH][4];

    int seg = blockIdx.x % Sseg;
    int bk  = blockIdx.x / Sseg;
    int k   = bk % Kk;
    int c   = threadIdx.x; // 96 threads

    float A[16];
    #pragma unroll
    for (int n = 0; n < 16; n++) A[n] = -__expf(A_logs[(k*Cc + c)*Nn + n]);
    bool fast = true;
    #pragma unroll
    for (int n = 1; n < 16; n++) {
        float ratio = A[n] / A[0];
        if (fabsf(ratio - (float)(n+1)) > 1e-5f*(float)(n+1)) fast = false;
    }

    float h[16];
    int base = bk*Ls + seg*Tseg;
    if (PASSB) {
        const float* h0p = &g_h0[((bk*Sseg + seg)*Cc + c)*Nn];
        #pragma unroll
        for (int n = 0; n < 16; n++) h[n] = h0p[n];
    } else {
        #pragma unroll
        for (int n = 0; n < 16; n++) h[n] = 0.f;
    }
    float sumd = 0.f;

    for (int t0 = 0; t0 < Tseg; t0 += CH) {
        __syncthreads();
        #pragma unroll
        for (int i = 0; i < CH; i++) {
            int gi = base + t0 + i;
            sD[i][c] = g_delta[gi*Cc + c];
            sU[i][c] = g_du[gi*Cc + c];
        }
        for (int idx = c; idx < CH*4; idx += Cc) {
            int i = idx >> 2, q = idx & 3;
            int gi = base + t0 + i;
            sB[i][q] = reinterpret_cast<const float4*>(g_Bv)[gi*4 + q];
            if (PASSB)
                sCs[i][q] = reinterpret_cast<const float4*>(g_Cv)[gi*4 + q];
        }
        __syncthreads();

        #pragma unroll 4
        for (int i = 0; i < CH; i++) {
            float delta = sD[i][c];
            float du    = sU[i][c];
            if (!PASSB) sumd += delta;
            float dA[16];
            float w = __expf(delta * A[0]);
            if (fast) {
                float w2 = w*w, w4 = w2*w2, w8 = w4*w4;
                dA[0]=w;      dA[1]=w2;     dA[2]=w2*w;  dA[3]=w4;
                dA[4]=w4*w;   dA[5]=w4*w2;  dA[6]=dA[5]*w; dA[7]=w8;
                #pragma unroll
                for (int n = 0; n < 8; n++) dA[8+n] = w8*dA[n];
            } else {
                dA[0] = w;
                #pragma unroll
                for (int n = 1; n < 16; n++) dA[n] = __expf(delta * A[n]);
            }
            const float* Bp = reinterpret_cast<const float*>(&sB[i][0]);
            #pragma unroll
            for (int n = 0; n < 16; n++) h[n] = dA[n]*h[n] + du*Bp[n];
            if (PASSB) {
                const float* Cp = reinterpret_cast<const float*>(&sCs[i][0]);
                float y0=0.f,y1=0.f,y2=0.f,y3=0.f;
                #pragma unroll
                for (int n = 0; n < 16; n += 4) {
                    y0 += h[n+0]*Cp[n+0];
                    y1 += h[n+1]*Cp[n+1];
                    y2 += h[n+2]*Cp[n+2];
                    y3 += h[n+3]*Cp[n+3];
                }
                g_y[(base + t0 + i)*Cc + c] = (y0+y1) + (y2+y3);
            }
        }
    }

    if (!PASSB) {
        int hb = (bk*Sseg + seg)*Cc + c;
        #pragma unroll
        for (int n = 0; n < 16; n++) g_hend[hb*Nn + n] = h[n];
        g_sumd[hb] = sumd;
    }
}

// ---------------- K3b: combine segment states --------------------------------
__global__ void k_combine(const float* __restrict__ A_logs)
{
    int id = blockIdx.x*128 + threadIdx.x;    // B*K*C*N = 12288 threads
    if (id >= Bsz*Kk*Cc*Nn) return;
    int bk = id / (Cc*Nn);
    int rem = id % (Cc*Nn);
    int c = rem / Nn, n = rem % Nn;
    int k = bk % Kk;
    float An = -__expf(A_logs[(k*Cc + c)*Nn + n]);
    float h = 0.f;
    for (int s = 0; s < Sseg; s++) {
        int hb = (bk*Sseg + s)*Cc + c;
        g_h0[hb*Nn + n] = h;
        float P = __expf(An * g_sumd[hb]);
        h = P*h + g_hend[hb*Nn + n];
    }
}

// ---------------- K4: combine 4 directions + D*u -> att (b,l,c) --------------
__global__ void k_comb_att(const float* __restrict__ Ds)
{
    int g = blockIdx.x*256 + threadIdx.x;
    if (g >= Bsz*Ls*Cc) return;
    int b = g / (Ls*Cc);
    int r = g % (Ls*Cc);
    int l = r / Cc, c = r % Cc;
    int hh = l >> 6, ww = l & 63;
    int t1 = ww*64 + hh;
    float Dsum = Ds[c] + Ds[Cc + c] + Ds[2*Cc + c] + Ds[3*Cc + c];
    int b4 = b*Kk;
    float att =
        g_y[((b4+0)*Ls + l)*Cc + c] +
        g_y[((b4+1)*Ls + t1)*Cc + c] +
        g_y[((b4+2)*Ls + (4095 - l))*Cc + c] +
        g_y[((b4+3)*Ls + (4095 - t1))*Cc + c] +
        Dsum * g_v[(b*Cc + c)*Ls + l];
    g_att[(b*Ls + l)*Cc + c] = att;
}

// ---------------- K5: depthwise 3x3 + BN + GELU + pooled sum -----------------
__global__ void k_conv(const float* __restrict__ dw_w, const float* __restrict__ dw_b,
                       const float* __restrict__ bn1_g, const float* __restrict__ bn1_b)
{
    __shared__ float sIm[66][66];
    __shared__ float red[128];
    int b = blockIdx.x / Cc;
    int c = blockIdx.x % Cc;
    int tid = threadIdx.x; // 128 threads

    for (int idx = tid; idx < 66*66; idx += 128)
        (&sIm[0][0])[idx] = 0.f;
    __syncthreads();
    const float* vp = &g_v[(b*Cc + c)*Ls];
    for (int idx = tid; idx < Ls; idx += 128)
        sIm[(idx>>6) + 1][(idx & 63) + 1] = vp[idx];

    float wgt[9];
    #pragma unroll
    for (int j = 0; j < 9; j++) wgt[j] = dw_w[c*9 + j];
    float bias = dw_b[c];
    float s1 = bn1_g[c] * rsqrtf(1.0f + 1e-5f);
    float sh = bn1_b[c];
    __syncthreads();

    float lsum = 0.f;
    for (int idx = tid; idx < Ls; idx += 128) {
        int hh = idx >> 6, ww = idx & 63;
        float acc = 0.f;
        #pragma unroll
        for (int dy = 0; dy < 3; dy++)
            #pragma unroll
            for (int dx = 0; dx < 3; dx++)
                acc += sIm[hh+dy][ww+dx]*wgt[dy*3+dx];
        float xv = (acc + bias)*s1 + sh;
        float gl = xv * normcdff(xv);
        g_convx[(b*Cc + c)*Ls + idx] = gl;
        lsum += gl;
    }
    red[tid] = lsum;
    __syncthreads();
    for (int s = 64; s > 0; s >>= 1) {
        if (tid < s) red[tid] += red[tid + s];
        __syncthreads();
    }
    if (tid == 0) g_pool[b*Cc + c] = red[0];
}

// ---------------- K6: channel gate -------------------------------------------
__global__ void k_chan(const float* __restrict__ ci_w1, const float* __restrict__ ci_b1,
                       const float* __restrict__ ci_bn_g, const float* __restrict__ ci_bn_b,
                       const float* __restrict__ ci_w2, const float* __restrict__ ci_b2)
{
    __shared__ float spool[96];
    __shared__ float sz[12];
    int b = blockIdx.x;
    int c = threadIdx.x; // 96
    spool[c] = g_pool[b*Cc + c] * (1.0f/4096.0f);
    __syncthreads();
    if (c < 12) {
        float acc = 0.f;
        #pragma unroll
        for (int cp = 0; cp < 96; cp++) acc += ci_w1[c*96 + cp]*spool[cp];
        acc += ci_b1[c];
        float z = acc * (ci_bn_g[c]*rsqrtf(1.0f + 1e-5f)) + ci_bn_b[c];
        sz[c] = z * normcdff(z);
    }
    __syncthreads();
    float cm = ci_b2[c];
    #pragma unroll
    for (int j = 0; j < 12; j++) cm += ci_w2[c*12 + j]*sz[j];
    g_cmsig[b*Cc + c] = sigmoidf_(cm);
}

// ---------------- K7: spatial gate + combine + output GEMM -------------------
__global__ void k_final(const float* __restrict__ si_w1, const float* __restrict__ si_b1,
                        const float* __restrict__ si_bn_g, const float* __restrict__ si_bn_b,
                        const float* __restrict__ si_w2, const float* __restrict__ si_b2,
                        const float* __restrict__ proj_w, const float* __restrict__ proj_b,
                        float* __restrict__ out)
{
    __shared__ float sAtt[16][97];
    __shared__ float sProjT[96][97];
    __shared__ float ssw[6][96];
    __shared__ float st1[16][8];
    __shared__ float sml[16];
    __shared__ float cms[96];

    int tiles = Ls/16;
    int b  = blockIdx.x / tiles;
    int l0 = (blockIdx.x % tiles)*16;
    int c  = threadIdx.x; // 96

    for (int idx = c; idx < 96*96; idx += 96)
        sProjT[idx % 96][idx / 96] = proj_w[idx]; // sProjT[c'][c] = proj_w[c][c']
    for (int idx = c; idx < 6*96; idx += 96)
        (&ssw[0][0])[idx] = si_w1[idx];
    cms[c] = g_cmsig[b*Cc + c];
    #pragma unroll
    for (int i = 0; i < 16; i++)
        sAtt[i][c] = g_att[(b*Ls + l0 + i)*Cc + c];
    __syncthreads();

    { // spatial MLP hidden: 16 l * 6 j = 96 tasks
        int i = c / 6, j = c % 6;
        float acc = 0.f;
        #pragma unroll
        for (int cp = 0; cp < 96; cp++) acc += sAtt[i][cp]*ssw[j][cp];
        acc += si_b1[j];
        float z = acc * (si_bn_g[j]*rsqrtf(1.0f + 1e-5f)) + si_bn_b[j];
        st1[i][j] = z * normcdff(z);
    }
    __syncthreads();
    if (c < 16) {
        float sm = si_b2[0];
        #pragma unroll
        for (int j = 0; j < 6; j++) sm += st1[c][j]*si_w2[j];
        sml[c] = sigmoidf_(sm);
    }
    __syncthreads();

    #pragma unroll
    for (int i = 0; i < 16; i++) {
        float fin = sAtt[i][c]*cms[c] + sml[i]*g_convx[(b*Cc + c)*Ls + l0 + i];
        sAtt[i][c] = fin;
    }
    __syncthreads();

    float pb = proj_b[c];
    for (int i = 0; i < 16; i++) {
        float acc = pb;
        #pragma unroll
        for (int cp = 0; cp < 96; cp++) acc += sAtt[i][cp]*sProjT[cp][c];
        out[(b*Ls + l0 + i)*Cc + c] = acc;
    }
}

// ---------------- launcher ----------------------------------------------------
extern "C" void kernel_launch(void* const* d_in, const int* in_sizes, int n_in,
                              void* d_out, int out_size)
{
    const float* x        = (const float*)d_in[0];
    const float* qkv_w    = (const float*)d_in[3];
    const float* proj_w   = (const float*)d_in[4];
    const float* proj_b   = (const float*)d_in[5];
    const float* dw_w     = (const float*)d_in[6];
    const float* dw_b     = (const float*)d_in[7];
    const float* bn1_g    = (const float*)d_in[8];
    const float* bn1_b    = (const float*)d_in[9];
    const float* ci_w1    = (const float*)d_in[10];
    const float* ci_b1    = (const float*)d_in[11];
    const float* ci_bn_g  = (const float*)d_in[12];
    const float* ci_bn_b  = (const float*)d_in[13];
    const float* ci_w2    = (const float*)d_in[14];
    const float* ci_b2    = (const float*)d_in[15];
    const float* si_w1    = (const float*)d_in[16];
    const float* si_b1    = (const float*)d_in[17];
    const float* si_bn_g  = (const float*)d_in[18];
    const float* si_bn_b  = (const float*)d_in[19];
    const float* si_w2    = (const float*)d_in[20];
    const float* si_b2    = (const float*)d_in[21];
    const float* x_proj_w = (const float*)d_in[22];
    const float* dt_w     = (const float*)d_in[23];
    const float* dt_b     = (const float*)d_in[24];
    const float* A_logs   = (const float*)d_in[25];
    const float* Ds       = (const float*)d_in[26];
    float* out = (float*)d_out;

    k_qkv<<<Bsz*(Ls/32), 96>>>(x, qkv_w);
    k_proj<<<Bsz*Kk*(Ls/32), 96>>>(x_proj_w, dt_w, dt_b);
    k_scan<false><<<Bsz*Kk*Sseg, 96>>>(A_logs);
    k_combine<<<(Bsz*Kk*Cc*Nn + 127)/128, 128>>>(A_logs);
    k_scan<true><<<Bsz*Kk*Sseg, 96>>>(A_logs);
    k_comb_att<<<(Bsz*Ls*Cc)/256, 256>>>(Ds);
    k_conv<<<Bsz*Cc, 128>>>(dw_w, dw_b, bn1_g, bn1_b);
    k_chan<<<Bsz, 96>>>(ci_w1, ci_b1, ci_bn_g, ci_bn_b, ci_w2, ci_b2);
    k_final<<<Bsz*(Ls/16), 96>>>(si_w1, si_b1, si_bn_g, si_bn_b, si_w2, si_b2,
                                 proj_w, proj_b, out);
}

// round 2
// speedup vs baseline: 1.4139x; 1.4139x over previous
#include <cuda_runtime.h>
#include <cuda_bf16.h>
#include <math.h>

// Problem constants (fixed by setup_inputs)
#define Bsz 2
#define Hh  64
#define Ww  64
#define Ls  4096      // H*W
#define Cc  96
#define Kk  4
#define Nn  16
#define Rr  6
#define Sseg 64       // segments
#define Tseg 64       // steps per segment (Sseg*Tseg = L)
#define CH  16        // scan chunk staged through smem

// ---------------- scratch (static device globals; no allocation) -------------
__device__ float g_v[Bsz*Cc*Ls];          // v_img (b,c,l)   l = h*64+w
__device__ float g_vw[Bsz*Cc*Ls];         // transposed      t = w*64+h -> v[h*64+w]
__device__ float g_delta[Bsz*Kk*Ls*Cc];   // (b,k,t,c)
__device__ float g_du[Bsz*Kk*Ls*Cc];      // delta*u
__device__ float g_Bv[Bsz*Kk*Ls*Nn];      // (b,k,t,n)
__device__ float g_Cv[Bsz*Kk*Ls*Nn];
__device__ float g_y[Bsz*Kk*Ls*Cc];       // scan output (b,k,t,c)
__device__ float g_hend[Bsz*Kk*Sseg*Cc*Nn];
__device__ float g_h0[Bsz*Kk*Sseg*Cc*Nn];
__device__ float g_sumd[Bsz*Kk*Sseg*Cc];
__device__ float g_convx[Bsz*Cc*Ls];      // (b,c,l)
__device__ float g_fin[Bsz*Ls*Cc];        // gated sum (b,l,c)
__device__ float g_pool[Bsz*Cc];

__device__ __forceinline__ float sigmoidf_(float x){ return 1.0f/(1.0f+__expf(-x)); }

// ---------------- K1: v_img = (x @ qkv_w^T) -> (b,c,l) -----------------------
__global__ void k_qkv(const float* __restrict__ x, const float* __restrict__ qkv_w)
{
    __shared__ float sx[32][97];
    __shared__ float sw[96][97];
    int blk = blockIdx.x;
    int b   = blk / (Ls/32);
    int l0  = (blk % (Ls/32)) * 32;
    int tid = threadIdx.x;       // 192
    int c    = tid % 96;
    int half = tid / 96;

    for (int idx = tid; idx < 96*96; idx += 192)
        sw[idx/96][idx%96] = qkv_w[idx];
    for (int i = half; i < 32; i += 2)
        sx[i][c] = x[(b*Ls + l0 + i)*Cc + c];
    __syncthreads();

    for (int l = half*16; l < half*16 + 16; l += 4) {
        float a0=0.f,a1=0.f,a2=0.f,a3=0.f;
        #pragma unroll
        for (int cp = 0; cp < 96; cp++) {
            float wv = sw[c][cp];
            a0 += sx[l+0][cp]*wv;
            a1 += sx[l+1][cp]*wv;
            a2 += sx[l+2][cp]*wv;
            a3 += sx[l+3][cp]*wv;
        }
        float4 o = make_float4(a0,a1,a2,a3);
        *reinterpret_cast<float4*>(&g_v[(b*Cc + c)*Ls + l0 + l]) = o;
    }
}

// ---------------- K1b: per-plane 64x64 transpose -> g_vw ---------------------
__global__ void k_tr()
{
    __shared__ float s[64][65];
    int plane = blockIdx.x;             // b*Cc + c  (192 planes)
    const float* src = &g_v[plane*Ls];
    float*       dst = &g_vw[plane*Ls];
    int tid = threadIdx.x;              // 256
    for (int idx = tid; idx < 4096; idx += 256)
        s[idx>>6][idx&63] = src[idx];
    __syncthreads();
    for (int idx = tid; idx < 4096; idx += 256)
        dst[idx] = s[idx&63][idx>>6];   // dst[w*64+h] = v[h*64+w]
}

// ---------------- K2: projections (x_dbl -> delta, du, B, C) -----------------
__global__ void k_proj(const float* __restrict__ x_proj_w,
                       const float* __restrict__ dt_w,
                       const float* __restrict__ dt_b)
{
    __shared__ float sxs[32][97];
    __shared__ float swp[38][97];
    __shared__ float sxd[32][40];

    int tiles = Ls/32;
    int tile = blockIdx.x % tiles;
    int k    = (blockIdx.x / tiles) % Kk;
    int b    = blockIdx.x / (tiles*Kk);
    int c    = threadIdx.x;  // 96 threads
    int t0   = tile*32;

    for (int idx = c; idx < 38*96; idx += 96)
        swp[idx/96][idx%96] = x_proj_w[k*38*96 + idx];
    float wdt[6];
    #pragma unroll
    for (int r = 0; r < 6; r++) wdt[r] = dt_w[(k*Cc + c)*Rr + r];
    float dtb = dt_b[k*Cc + c];

    // per-thread contiguous row loads in scan order
    const float* srcp = ((k & 1) ? g_vw : g_v) + (b*Cc + c)*Ls;
    if (k < 2) {
        const float4* p4 = reinterpret_cast<const float4*>(srcp + t0);
        #pragma unroll
        for (int j = 0; j < 8; j++) {
            float4 v4 = p4[j];
            sxs[4*j+0][c]=v4.x; sxs[4*j+1][c]=v4.y; sxs[4*j+2][c]=v4.z; sxs[4*j+3][c]=v4.w;
        }
    } else {
        const float4* p4 = reinterpret_cast<const float4*>(srcp + (4096 - t0 - 32));
        #pragma unroll
        for (int j = 0; j < 8; j++) {
            float4 v4 = p4[j];
            int ib = 31 - 4*j;
            sxs[ib][c]=v4.x; sxs[ib-1][c]=v4.y; sxs[ib-2][c]=v4.z; sxs[ib-3][c]=v4.w;
        }
    }
    __syncthreads();

    // x_dbl = xs @ x_proj_w^T  : tasks (j, igroup of 4)
    for (int p = c; p < 38*8; p += 96) {
        int j = p % 38, i0 = (p / 38)*4;
        float a0=0.f,a1=0.f,a2=0.f,a3=0.f;
        #pragma unroll
        for (int cp = 0; cp < 96; cp++) {
            float wv = swp[j][cp];
            a0 += sxs[i0+0][cp]*wv;
            a1 += sxs[i0+1][cp]*wv;
            a2 += sxs[i0+2][cp]*wv;
            a3 += sxs[i0+3][cp]*wv;
        }
        sxd[i0+0][j]=a0; sxd[i0+1][j]=a1; sxd[i0+2][j]=a2; sxd[i0+3][j]=a3;
    }
    __syncthreads();

    int bk = b*Kk + k;
    #pragma unroll 4
    for (int i = 0; i < 32; i++) {
        float acc = dtb;
        #pragma unroll
        for (int r = 0; r < 6; r++) acc += sxd[i][r]*wdt[r];
        float delta = (acc > 20.f) ? acc : log1pf(__expf(acc));
        int gi = (bk*Ls + t0 + i);
        g_delta[gi*Cc + c] = delta;
        g_du[gi*Cc + c]    = delta * sxs[i][c];
    }
    for (int p = c; p < 32*16; p += 96) {
        int i = p / 16, n = p % 16;
        int gi = (bk*Ls + t0 + i);
        g_Bv[gi*Nn + n] = sxd[i][6 + n];
        g_Cv[gi*Nn + n] = sxd[i][22 + n];
    }
}

// ---------------- K3: segmented selective scan (double-buffered) -------------
template<bool PASSB>
__global__ void k_scan(const float* __restrict__ A_logs)
{
    __shared__ float  sD[2][CH][Cc];
    __shared__ float  sU[2][CH][Cc];
    __shared__ float4 sB[2][CH][4];
    __shared__ float4 sCs[2][CH][4];

    int seg = blockIdx.x % Sseg;
    int bk  = blockIdx.x / Sseg;
    int k   = bk % Kk;
    int c   = threadIdx.x; // 96 threads
    int base = bk*Ls + seg*Tseg;

    float A[16];
    #pragma unroll
    for (int n = 0; n < 16; n++) A[n] = -__expf(A_logs[(k*Cc + c)*Nn + n]);
    bool fast = true;
    #pragma unroll
    for (int n = 1; n < 16; n++) {
        float ratio = A[n] / A[0];
        if (fabsf(ratio - (float)(n+1)) > 1e-5f*(float)(n+1)) fast = false;
    }

    float h[16];
    if (PASSB) {
        const float* h0p = &g_h0[((bk*Sseg + seg)*Cc + c)*Nn];
        #pragma unroll
        for (int n = 0; n < 16; n++) h[n] = h0p[n];
    } else {
        #pragma unroll
        for (int n = 0; n < 16; n++) h[n] = 0.f;
    }
    float sumd = 0.f;

    const int NCH = Tseg/CH;   // 4

    // chunk loader
    auto load_chunk = [&](int chk, int buf) {
        int gbase = base + chk*CH;
        #pragma unroll
        for (int i = 0; i < CH; i++) {
            int gi = gbase + i;
            sD[buf][i][c] = g_delta[gi*Cc + c];
            sU[buf][i][c] = g_du[gi*Cc + c];
        }
        for (int idx = c; idx < CH*4; idx += Cc) {
            int i = idx >> 2, q = idx & 3;
            int gi = gbase + i;
            sB[buf][i][q] = reinterpret_cast<const float4*>(g_Bv)[gi*4 + q];
            if (PASSB)
                sCs[buf][i][q] = reinterpret_cast<const float4*>(g_Cv)[gi*4 + q];
        }
    };

    load_chunk(0, 0);
    __syncthreads();

    for (int ch = 0; ch < NCH; ch++) {
        int cur = ch & 1;
        if (ch + 1 < NCH) load_chunk(ch + 1, cur ^ 1);

        #pragma unroll 4
        for (int i = 0; i < CH; i++) {
            float delta = sD[cur][i][c];
            float du    = sU[cur][i][c];
            if (!PASSB) sumd += delta;
            float dA[16];
            float w = __expf(delta * A[0]);
            if (fast) {
                float w2 = w*w, w4 = w2*w2, w8 = w4*w4;
                dA[0]=w;      dA[1]=w2;     dA[2]=w2*w;    dA[3]=w4;
                dA[4]=w4*w;   dA[5]=w4*w2;  dA[6]=dA[5]*w; dA[7]=w8;
                #pragma unroll
                for (int n = 0; n < 8; n++) dA[8+n] = w8*dA[n];
            } else {
                dA[0] = w;
                #pragma unroll
                for (int n = 1; n < 16; n++) dA[n] = __expf(delta * A[n]);
            }
            const float* Bp = reinterpret_cast<const float*>(&sB[cur][i][0]);
            #pragma unroll
            for (int n = 0; n < 16; n++) h[n] = dA[n]*h[n] + du*Bp[n];
            if (PASSB) {
                const float* Cp = reinterpret_cast<const float*>(&sCs[cur][i][0]);
                float y0=0.f,y1=0.f,y2=0.f,y3=0.f;
                #pragma unroll
                for (int n = 0; n < 16; n += 4) {
                    y0 += h[n+0]*Cp[n+0];
                    y1 += h[n+1]*Cp[n+1];
                    y2 += h[n+2]*Cp[n+2];
                    y3 += h[n+3]*Cp[n+3];
                }
                g_y[(base + ch*CH + i)*Cc + c] = (y0+y1) + (y2+y3);
            }
        }
        __syncthreads();
    }

    if (!PASSB) {
        int hb = (bk*Sseg + seg)*Cc + c;
        #pragma unroll
        for (int n = 0; n < 16; n++) g_hend[hb*Nn + n] = h[n];
        g_sumd[hb] = sumd;
    }
}

// ---------------- K3b: combine segment states (batched loads) ----------------
__global__ void k_combine(const float* __restrict__ A_logs)
{
    int id = blockIdx.x*256 + threadIdx.x;    // B*K*C*N = 12288 threads
    if (id >= Bsz*Kk*Cc*Nn) return;
    int bk = id / (Cc*Nn);
    int rem = id % (Cc*Nn);
    int c = rem / Nn, n = rem % Nn;
    int k = bk % Kk;
    float An = -__expf(A_logs[(k*Cc + c)*Nn + n]);

    float P[Sseg], he[Sseg];
    #pragma unroll
    for (int s = 0; s < Sseg; s++) {
        int hb = (bk*Sseg + s)*Cc + c;
        P[s]  = g_sumd[hb];
        he[s] = g_hend[hb*Nn + n];
    }
    #pragma unroll
    for (int s = 0; s < Sseg; s++) P[s] = __expf(An * P[s]);

    float h = 0.f;
    #pragma unroll
    for (int s = 0; s < Sseg; s++) {
        g_h0[((bk*Sseg + s)*Cc + c)*Nn + n] = h;
        h = P[s]*h + he[s];
    }
}

// ---------------- K5: depthwise 3x3 + BN + GELU + pooled sum -----------------
__global__ void k_conv(const float* __restrict__ dw_w, const float* __restrict__ dw_b,
                       const float* __restrict__ bn1_g, const float* __restrict__ bn1_b)
{
    __shared__ float sIm[66][66];
    __shared__ float red[256];
    int b = blockIdx.x / Cc;
    int c = blockIdx.x % Cc;
    int tid = threadIdx.x; // 256 threads

    for (int idx = tid; idx < 66*66; idx += 256)
        (&sIm[0][0])[idx] = 0.f;
    __syncthreads();
    const float* vp = &g_v[(b*Cc + c)*Ls];
    for (int idx = tid; idx < Ls; idx += 256)
        sIm[(idx>>6) + 1][(idx & 63) + 1] = vp[idx];

    float wgt[9];
    #pragma unroll
    for (int j = 0; j < 9; j++) wgt[j] = dw_w[c*9 + j];
    float bias = dw_b[c];
    float s1 = bn1_g[c] * rsqrtf(1.0f + 1e-5f);
    float sh = bn1_b[c];
    __syncthreads();

    float lsum = 0.f;
    for (int idx = tid; idx < Ls; idx += 256) {
        int hh = idx >> 6, ww = idx & 63;
        float acc = 0.f;
        #pragma unroll
        for (int dy = 0; dy < 3; dy++)
            #pragma unroll
            for (int dx = 0; dx < 3; dx++)
                acc += sIm[hh+dy][ww+dx]*wgt[dy*3+dx];
        float xv = (acc + bias)*s1 + sh;
        float gl = xv * normcdff(xv);
        g_convx[(b*Cc + c)*Ls + idx] = gl;
        lsum += gl;
    }
    red[tid] = lsum;
    __syncthreads();
    for (int s = 128; s > 0; s >>= 1) {
        if (tid < s) red[tid] += red[tid + s];
        __syncthreads();
    }
    if (tid == 0) g_pool[b*Cc + c] = red[0];
}

// ---------------- K6: combine dirs + channel gate + spatial gate -> g_fin ----
__global__ void k_att(const float* __restrict__ Ds,
                      const float* __restrict__ ci_w1, const float* __restrict__ ci_b1,
                      const float* __restrict__ ci_bn_g, const float* __restrict__ ci_bn_b,
                      const float* __restrict__ ci_w2, const float* __restrict__ ci_b2,
                      const float* __restrict__ si_w1, const float* __restrict__ si_b1,
                      const float* __restrict__ si_bn_g, const float* __restrict__ si_bn_b,
                      const float* __restrict__ si_w2, const float* __restrict__ si_b2)
{
    __shared__ float sAtt[32][97];
    __shared__ float sV[96][33];
    __shared__ float sCx[96][33];
    __shared__ float spool[96];
    __shared__ float szc[12];
    __shared__ float ssw[6][96];
    __shared__ float st1[32][8];
    __shared__ float sml[32];

    int tiles = Ls/32; // 128
    int b  = blockIdx.x / tiles;
    int l0 = (blockIdx.x % tiles)*32;
    int c  = threadIdx.x; // 96

    spool[c] = g_pool[b*Cc + c] * (1.0f/4096.0f);
    for (int idx = c; idx < 6*96; idx += 96)
        (&ssw[0][0])[idx] = si_w1[idx];

    {   // own-column contiguous row loads
        const float4* vp = reinterpret_cast<const float4*>(&g_v[(b*Cc+c)*Ls + l0]);
        const float4* cp = reinterpret_cast<const float4*>(&g_convx[(b*Cc+c)*Ls + l0]);
        #pragma unroll
        for (int j = 0; j < 8; j++) {
            float4 t = vp[j];
            sV[c][4*j]=t.x; sV[c][4*j+1]=t.y; sV[c][4*j+2]=t.z; sV[c][4*j+3]=t.w;
            float4 u = cp[j];
            sCx[c][4*j]=u.x; sCx[c][4*j+1]=u.y; sCx[c][4*j+2]=u.z; sCx[c][4*j+3]=u.w;
        }
    }

    float Dsum = Ds[c] + Ds[Cc + c] + Ds[2*Cc + c] + Ds[3*Cc + c];
    int hh = l0 >> 6, ww0 = l0 & 63;
    int b4 = b*Kk;
    #pragma unroll 8
    for (int i = 0; i < 32; i++) {
        int l = l0 + i;
        int t1 = (ww0 + i)*64 + hh;
        float att =
            g_y[((b4+0)*Ls + l)*Cc + c] +
            g_y[((b4+1)*Ls + t1)*Cc + c] +
            g_y[((b4+2)*Ls + (4095 - l))*Cc + c] +
            g_y[((b4+3)*Ls + (4095 - t1))*Cc + c] +
            Dsum * sV[c][i];
        sAtt[i][c] = att;
    }
    __syncthreads();

    // channel-gate hidden (12 tasks) + spatial hidden (32*6=192 tasks)
    if (c < 12) {
        float acc = ci_b1[c];
        #pragma unroll
        for (int cp = 0; cp < 96; cp++) acc += ci_w1[c*96 + cp]*spool[cp];
        float z = acc * (ci_bn_g[c]*rsqrtf(1.0f + 1e-5f)) + ci_bn_b[c];
        szc[c] = z * normcdff(z);
    }
    for (int p = c; p < 192; p += 96) {
        int i = p / 6, j = p % 6;
        float acc = si_b1[j];
        #pragma unroll
        for (int cp = 0; cp < 96; cp++) acc += sAtt[i][cp]*ssw[j][cp];
        float z = acc * (si_bn_g[j]*rsqrtf(1.0f + 1e-5f)) + si_bn_b[j];
        st1[i][j] = z * normcdff(z);
    }
    __syncthreads();

    float cmv = ci_b2[c];
    #pragma unroll
    for (int j = 0; j < 12; j++) cmv += ci_w2[c*12 + j]*szc[j];
    float cms = sigmoidf_(cmv);
    if (c < 32) {
        float sm = si_b2[0];
        #pragma unroll
        for (int j = 0; j < 6; j++) sm += st1[c][j]*si_w2[j];
        sml[c] = sigmoidf_(sm);
    }
    __syncthreads();

    #pragma unroll 8
    for (int i = 0; i < 32; i++) {
        g_fin[(b*Ls + l0 + i)*Cc + c] = sAtt[i][c]*cms + sml[i]*sCx[c][i];
    }
}

// ---------------- K7: output GEMM -------------------------------------------
__global__ void k_out(const float* __restrict__ proj_w, const float* __restrict__ proj_b,
                      float* __restrict__ out)
{
    __shared__ float sProjT[96][97];   // [cp][c_out]
    __shared__ float sFin[16][97];

    int tiles = Ls/16; // 256
    int b  = blockIdx.x / tiles;
    int l0 = (blockIdx.x % tiles)*16;
    int c  = threadIdx.x; // 96

    for (int idx = c; idx < 96*96; idx += 96)
        sProjT[idx % 96][idx / 96] = proj_w[idx];
    #pragma unroll
    for (int i = 0; i < 16; i++)
        sFin[i][c] = g_fin[(b*Ls + l0 + i)*Cc + c];
    __syncthreads();

    float pb = proj_b[c];
    for (int i = 0; i < 16; i += 4) {
        float a0=pb,a1=pb,a2=pb,a3=pb;
        #pragma unroll
        for (int cp = 0; cp < 96; cp++) {
            float wv = sProjT[cp][c];
            a0 += sFin[i+0][cp]*wv;
            a1 += sFin[i+1][cp]*wv;
            a2 += sFin[i+2][cp]*wv;
            a3 += sFin[i+3][cp]*wv;
        }
        out[(b*Ls + l0 + i+0)*Cc + c] = a0;
        out[(b*Ls + l0 + i+1)*Cc + c] = a1;
        out[(b*Ls + l0 + i+2)*Cc + c] = a2;
        out[(b*Ls + l0 + i+3)*Cc + c] = a3;
    }
}

// ---------------- launcher ----------------------------------------------------
extern "C" void kernel_launch(void* const* d_in, const int* in_sizes, int n_in,
                              void* d_out, int out_size)
{
    const float* x        = (const float*)d_in[0];
    const float* qkv_w    = (const float*)d_in[3];
    const float* proj_w   = (const float*)d_in[4];
    const float* proj_b   = (const float*)d_in[5];
    const float* dw_w     = (const float*)d_in[6];
    const float* dw_b     = (const float*)d_in[7];
    const float* bn1_g    = (const float*)d_in[8];
    const float* bn1_b    = (const float*)d_in[9];
    const float* ci_w1    = (const float*)d_in[10];
    const float* ci_b1    = (const float*)d_in[11];
    const float* ci_bn_g  = (const float*)d_in[12];
    const float* ci_bn_b  = (const float*)d_in[13];
    const float* ci_w2    = (const float*)d_in[14];
    const float* ci_b2    = (const float*)d_in[15];
    const float* si_w1    = (const float*)d_in[16];
    const float* si_b1    = (const float*)d_in[17];
    const float* si_bn_g  = (const float*)d_in[18];
    const float* si_bn_b  = (const float*)d_in[19];
    const float* si_w2    = (const float*)d_in[20];
    const float* si_b2    = (const float*)d_in[21];
    const float* x_proj_w = (const float*)d_in[22];
    const float* dt_w     = (const float*)d_in[23];
    const float* dt_b     = (const float*)d_in[24];
    const float* A_logs   = (const float*)d_in[25];
    const float* Ds       = (const float*)d_in[26];
    float* out = (float*)d_out;

    k_qkv<<<Bsz*(Ls/32), 192>>>(x, qkv_w);
    k_tr<<<Bsz*Cc, 256>>>();
    k_proj<<<Bsz*Kk*(Ls/32), 96>>>(x_proj_w, dt_w, dt_b);
    k_scan<false><<<Bsz*Kk*Sseg, 96>>>(A_logs);
    k_combine<<<(Bsz*Kk*Cc*Nn + 255)/256, 256>>>(A_logs);
    k_scan<true><<<Bsz*Kk*Sseg, 96>>>(A_logs);
    k_conv<<<Bsz*Cc, 256>>>(dw_w, dw_b, bn1_g, bn1_b);
    k_att<<<Bsz*(Ls/32), 96>>>(Ds, ci_w1, ci_b1, ci_bn_g, ci_bn_b, ci_w2, ci_b2,
                               si_w1, si_b1, si_bn_g, si_bn_b, si_w2, si_b2);
    k_out<<<Bsz*(Ls/16), 96>>>(proj_w, proj_b, out);
}